// round 4
// baseline (speedup 1.0000x reference)
#include <cuda_runtime.h>
#include <math.h>

#define TT 8
#define NI 20000
#define NK 50000
#define FF 128
#define HH 256
#define OO 128
#define EE 500000
#define MAXS 512
#define CLUSTER 8

// ---------------- scratch (device globals; no allocation allowed) ----------------
__device__ int   g_item_flag[TT][NK];     // -1 empty, -2 marked, >=0 slot
__device__ int   g_item_mult[TT][NK];     // edge multiplicity (src,target) in e2
__device__ int   g_item_id[TT][MAXS];
__device__ int   g_item_cnt[TT][MAXS];    // e1 in-degree of needed item
__device__ float g_item_acc[TT][MAXS][FF];
__device__ float g_hitem[TT][MAXS][HH];
__device__ int   g_num_items[TT];
__device__ float g_accx[TT][FF];          // sum of x_item over target's e2 edges
__device__ int   g_edge_cnt[TT];
__device__ float g_gi[TT][3 * HH];
__device__ float g_hbuf[2][HH];
__device__ float g_rnn[TT][HH];

// ---------------- init / reset (R1-proven one-shot form) ----------------
__global__ void k_init() {
    int idx = blockIdx.x * blockDim.x + threadIdx.x;
    if (idx < TT * NK) {
        ((int*)g_item_flag)[idx] = -1;
        ((int*)g_item_mult)[idx] = 0;
    }
    if (idx < TT * MAXS * FF) ((float*)g_item_acc)[idx] = 0.0f;
    if (idx < TT * MAXS)      ((int*)g_item_cnt)[idx] = 0;
    if (idx < TT * FF)        ((float*)g_accx)[idx] = 0.0f;
    if (idx < TT) { g_edge_cnt[idx] = 0; g_num_items[idx] = 0; }
    if (idx < HH) g_hbuf[0][idx] = 0.0f;
}

// ---------------- pass A: scan e2 (R1-proven scalar strided form) ----------------
__global__ void k_scan_e2(const int* __restrict__ e2s, const int* __restrict__ e2d,
                          const float* __restrict__ x_item, const int* __restrict__ tgtp) {
    int t = blockIdx.y;
    int tgt = *tgtp;
    const int* d = e2d + (size_t)t * EE;
    const int* s = e2s + (size_t)t * EE;
    for (int e = blockIdx.x * blockDim.x + threadIdx.x; e < EE; e += gridDim.x * blockDim.x) {
        if (d[e] == tgt) {
            int src = s[e];
            atomicAdd(&g_edge_cnt[t], 1);
            atomicAdd(&g_item_mult[t][src], 1);
            int old = atomicExch(&g_item_flag[t][src], -2);
            if (old == -1) {
                int sl = atomicAdd(&g_num_items[t], 1);
                if (sl < MAXS) g_item_id[t][sl] = src;
            }
            const float* xr = x_item + ((size_t)t * NK + src) * FF;
            #pragma unroll 4
            for (int f = 0; f < FF; f++) atomicAdd(&g_accx[t][f], xr[f]);
        }
    }
}

// ---------------- pass A2: assign slot ids (R1-proven) ----------------
__global__ void k_assign() {
    int t = blockIdx.x;
    if (threadIdx.x == 0 && g_num_items[t] > MAXS) g_num_items[t] = MAXS;
    __syncthreads();
    int n = g_num_items[t];
    for (int k = threadIdx.x; k < n; k += blockDim.x)
        g_item_flag[t][g_item_id[t][k]] = k;
}

// ---------------- pass B: scan e1 (R1-proven scalar strided form) ----------------
__global__ void k_scan_e1(const int* __restrict__ e1s, const int* __restrict__ e1d,
                          const float* __restrict__ x_inf) {
    int t = blockIdx.y;
    const int* d = e1d + (size_t)t * EE;
    const int* s = e1s + (size_t)t * EE;
    for (int e = blockIdx.x * blockDim.x + threadIdx.x; e < EE; e += gridDim.x * blockDim.x) {
        int dst = d[e];
        int sl = g_item_flag[t][dst];
        if (sl >= 0) {
            atomicAdd(&g_item_cnt[t][sl], 1);
            int src = s[e];
            const float* xr = x_inf + ((size_t)t * NI + src) * FF;
            #pragma unroll 4
            for (int f = 0; f < FF; f++) atomicAdd(&g_item_acc[t][sl][f], xr[f]);
        }
    }
}

// ---------------- fused per-t: h_item slots + o_inf[target] + GRU input gates ----------------
__global__ void k_pert(const float* __restrict__ x_item, const float* __restrict__ x_inf,
                       const float* __restrict__ W1a_l, const float* __restrict__ b1a_l,
                       const float* __restrict__ W1a_r,
                       const float* __restrict__ W1b_l, const float* __restrict__ b1b_l,
                       const float* __restrict__ W1b_r,
                       const float* __restrict__ W2b_l, const float* __restrict__ b2b_l,
                       const float* __restrict__ W2b_r,
                       const float* __restrict__ W_ih, const float* __restrict__ b_ih,
                       const int* __restrict__ tgtp) {
    int t = blockIdx.x;
    int tid = threadIdx.x;
    __shared__ float mean[FF], xrow[FF], hinf[HH], meanh[HH], multw[MAXS], xs[OO];
    int n = g_num_items[t];
    if (n > MAXS) n = MAXS;

    // --- h_item for each needed slot ---
    for (int sl = 0; sl < n; sl++) {
        if (tid < FF) {
            float c = fmaxf((float)g_item_cnt[t][sl], 1.0f);
            mean[tid] = g_item_acc[t][sl][tid] / c;
            xrow[tid] = x_item[((size_t)t * NK + g_item_id[t][sl]) * FF + tid];
        }
        __syncthreads();
        int h = tid;
        float a = b1a_l[h];
        const float* wl = W1a_l + (size_t)h * FF;
        const float* wr = W1a_r + (size_t)h * FF;
        #pragma unroll 8
        for (int f = 0; f < FF; f++) a += mean[f] * wl[f] + xrow[f] * wr[f];
        g_hitem[t][sl][h] = fmaxf(a, 0.0f);
        __syncthreads();
    }

    // --- h_inf[target] + weighted mean of h_item over target's e2 edges ---
    int tgt = *tgtp;
    float ec = fmaxf((float)g_edge_cnt[t], 1.0f);
    if (tid < FF) {
        mean[tid] = g_accx[t][tid] / ec;
        xrow[tid] = x_inf[((size_t)t * NI + tgt) * FF + tid];
    }
    for (int k = tid; k < n; k += blockDim.x)
        multw[k] = (float)g_item_mult[t][g_item_id[t][k]];
    __syncthreads();
    {
        int h = tid;
        float v = b1b_l[h];
        const float* wl = W1b_l + (size_t)h * FF;
        const float* wr = W1b_r + (size_t)h * FF;
        #pragma unroll 8
        for (int f = 0; f < FF; f++) v += mean[f] * wl[f] + xrow[f] * wr[f];
        hinf[h] = fmaxf(v, 0.0f);
        float mh = 0.0f;
        for (int k = 0; k < n; k++) mh += multw[k] * g_hitem[t][k][h];
        meanh[h] = mh / ec;
    }
    __syncthreads();

    // --- o_inf[target] -> xs ---
    if (tid < OO) {
        int o = tid;
        float v = b2b_l[o];
        const float* wl = W2b_l + (size_t)o * HH;
        const float* wr = W2b_r + (size_t)o * HH;
        #pragma unroll 8
        for (int h2 = 0; h2 < HH; h2++) v += meanh[h2] * wl[h2] + hinf[h2] * wr[h2];
        xs[o] = v;
    }
    __syncthreads();

    // --- GRU input gates gi = W_ih @ seq[t] + b_ih ---
    for (int row = tid; row < 3 * HH; row += blockDim.x) {
        float v = b_ih[row];
        const float* w = W_ih + (size_t)row * OO;
        #pragma unroll 8
        for (int o = 0; o < OO; o++) v += w[o] * xs[o];
        g_gi[t][row] = v;
    }
}

// ---------------- fused GRU (8 steps) + head: one 8-block CLUSTER ----------------
__global__ void __cluster_dims__(CLUSTER, 1, 1) __launch_bounds__(256, 1)
k_gru_head(const float* __restrict__ W_hh, const float* __restrict__ b_hh,
           const float* __restrict__ W_att, const float* __restrict__ b_att,
           const float* __restrict__ W_p1, const float* __restrict__ b_p1,
           const float* __restrict__ W_p2, const float* __restrict__ b_p2,
           float* __restrict__ out) {
    int wid = threadIdx.x >> 5;
    int lane = threadIdx.x & 31;
    int row0 = (blockIdx.x * 8 + wid) * 4;   // 4 rows per warp

    float wt[4][3][8];
    float bh[4][3];
    #pragma unroll
    for (int r = 0; r < 4; r++) {
        int row = row0 + r;
        #pragma unroll
        for (int j = 0; j < 8; j++) {
            int k = lane + 32 * j;
            wt[r][0][j] = __ldg(W_hh + (size_t)row * HH + k);
            wt[r][1][j] = __ldg(W_hh + (size_t)(HH + row) * HH + k);
            wt[r][2][j] = __ldg(W_hh + (size_t)(2 * HH + row) * HH + k);
        }
        bh[r][0] = __ldg(b_hh + row);
        bh[r][1] = __ldg(b_hh + HH + row);
        bh[r][2] = __ldg(b_hh + 2 * HH + row);
    }

    for (int t = 0; t < TT; t++) {
        const float* hp = g_hbuf[t & 1];
        float hv[8];
        #pragma unroll
        for (int j = 0; j < 8; j++) hv[j] = hp[lane + 32 * j];
        #pragma unroll
        for (int r = 0; r < 4; r++) {
            float sr = 0.0f, sz = 0.0f, sn = 0.0f;
            #pragma unroll
            for (int j = 0; j < 8; j++) {
                sr += wt[r][0][j] * hv[j];
                sz += wt[r][1][j] * hv[j];
                sn += wt[r][2][j] * hv[j];
            }
            #pragma unroll
            for (int off = 16; off > 0; off >>= 1) {
                sr += __shfl_down_sync(0xffffffffu, sr, off);
                sz += __shfl_down_sync(0xffffffffu, sz, off);
                sn += __shfl_down_sync(0xffffffffu, sn, off);
            }
            if (lane == 0) {
                int row = row0 + r;
                float rr = 1.0f / (1.0f + expf(-(g_gi[t][row] + sr + bh[r][0])));
                float zz = 1.0f / (1.0f + expf(-(g_gi[t][HH + row] + sz + bh[r][1])));
                float nn = tanhf(g_gi[t][2 * HH + row] + rr * (sn + bh[r][2]));
                float hn = (1.0f - zz) * nn + zz * hp[row];
                g_hbuf[(t + 1) & 1][row] = hn;
                g_rnn[t][row] = hn;
            }
        }
        __threadfence();
        asm volatile("barrier.cluster.arrive.aligned;" ::: "memory");
        asm volatile("barrier.cluster.wait.aligned;" ::: "memory");
    }

    // --- attention + prediction head (block 0 only; post-sync, L1 flushed) ---
    if (blockIdx.x != 0) return;
    __shared__ float att[TT], ctx[HH], red[HH];
    int tid = threadIdx.x;
    if (tid < TT) {
        float lg = b_att[0];
        for (int h = 0; h < HH; h++) lg += g_rnn[tid][h] * W_att[h];
        att[tid] = lg;
    }
    __syncthreads();
    if (tid == 0) {
        float m = att[0];
        for (int t = 1; t < TT; t++) m = fmaxf(m, att[t]);
        float s = 0.0f;
        for (int t = 0; t < TT; t++) { att[t] = expf(att[t] - m); s += att[t]; }
        for (int t = 0; t < TT; t++) att[t] /= s;
    }
    __syncthreads();
    {
        float c = 0.0f;
        #pragma unroll
        for (int t = 0; t < TT; t++) c += att[t] * g_rnn[t][tid];
        ctx[tid] = c;
    }
    __syncthreads();
    if (tid < HH / 2) {
        float v = b_p1[tid];
        const float* wp = W_p1 + (size_t)tid * HH;
        #pragma unroll 8
        for (int h = 0; h < HH; h++) v += wp[h] * ctx[h];
        v = fmaxf(v, 0.0f);
        red[tid] = v * W_p2[tid];
    }
    __syncthreads();
    if (tid == 0) {
        float s = b_p2[0];
        for (int j = 0; j < HH / 2; j++) s += red[j];
        out[0] = s;
    }
}

extern "C" void kernel_launch(void* const* d_in, const int* in_sizes, int n_in,
                              void* d_out, int out_size) {
    const float* x_inf  = (const float*)d_in[0];
    const float* x_item = (const float*)d_in[1];
    const int*   e1s    = (const int*)d_in[2];
    const int*   e1d    = (const int*)d_in[3];
    const int*   e2s    = (const int*)d_in[4];
    const int*   e2d    = (const int*)d_in[5];
    const int*   tgt    = (const int*)d_in[6];
    const float* W1a_l  = (const float*)d_in[7];
    const float* b1a_l  = (const float*)d_in[8];
    const float* W1a_r  = (const float*)d_in[9];
    const float* W1b_l  = (const float*)d_in[10];
    const float* b1b_l  = (const float*)d_in[11];
    const float* W1b_r  = (const float*)d_in[12];
    // d_in[13..15]: W2a_* (dead code — o_item unused by the head)
    const float* W2b_l  = (const float*)d_in[16];
    const float* b2b_l  = (const float*)d_in[17];
    const float* W2b_r  = (const float*)d_in[18];
    const float* W_ih   = (const float*)d_in[19];
    const float* W_hh   = (const float*)d_in[20];
    const float* b_ih   = (const float*)d_in[21];
    const float* b_hh   = (const float*)d_in[22];
    const float* W_att  = (const float*)d_in[23];
    const float* b_att  = (const float*)d_in[24];
    const float* W_p1   = (const float*)d_in[25];
    const float* b_p1   = (const float*)d_in[26];
    const float* W_p2   = (const float*)d_in[27];
    const float* b_p2   = (const float*)d_in[28];
    float* out = (float*)d_out;

    k_init<<<2048, 256>>>();
    dim3 gscan(512, TT);
    k_scan_e2<<<gscan, 256>>>(e2s, e2d, x_item, tgt);
    k_assign<<<TT, 256>>>();
    k_scan_e1<<<gscan, 256>>>(e1s, e1d, x_inf);
    k_pert<<<TT, 256>>>(x_item, x_inf, W1a_l, b1a_l, W1a_r, W1b_l, b1b_l, W1b_r,
                        W2b_l, b2b_l, W2b_r, W_ih, b_ih, tgt);
    k_gru_head<<<CLUSTER, 256>>>(W_hh, b_hh, W_att, b_att, W_p1, b_p1, W_p2, b_p2, out);
}

// round 5
// speedup vs baseline: 1.4636x; 1.4636x over previous
#include <cuda_runtime.h>
#include <math.h>

#define TT 8
#define NI 20000
#define NK 50000
#define FF 128
#define HH 256
#define OO 128
#define EE 500000
#define MAXS 512

// ---------------- scratch (device globals; no allocation allowed) ----------------
__device__ int   g_item_flag[TT][NK];     // -1 empty, -2 marked, >=0 slot
__device__ int   g_item_mult[TT][NK];     // edge multiplicity (src,target) in e2
__device__ int   g_item_id[TT][MAXS];
__device__ int   g_item_cnt[TT][MAXS];    // e1 in-degree of needed item
__device__ float g_item_acc[TT][MAXS][FF];
__device__ float g_hitem[TT][MAXS][HH];
__device__ int   g_num_items[TT];
__device__ float g_accx[TT][FF];          // sum of x_item over target's e2 edges
__device__ int   g_edge_cnt[TT];
__device__ float g_gi[TT][3 * HH];

// ---------------- init / reset (R1-proven one-shot form) ----------------
__global__ void k_init() {
    int idx = blockIdx.x * blockDim.x + threadIdx.x;
    if (idx < TT * NK) {
        ((int*)g_item_flag)[idx] = -1;
        ((int*)g_item_mult)[idx] = 0;
    }
    if (idx < TT * MAXS * FF) ((float*)g_item_acc)[idx] = 0.0f;
    if (idx < TT * MAXS)      ((int*)g_item_cnt)[idx] = 0;
    if (idx < TT * FF)        ((float*)g_accx)[idx] = 0.0f;
    if (idx < TT) { g_edge_cnt[idx] = 0; g_num_items[idx] = 0; }
}

// ---------------- pass A: scan e2 (R1-proven scalar strided form) ----------------
__global__ void k_scan_e2(const int* __restrict__ e2s, const int* __restrict__ e2d,
                          const float* __restrict__ x_item, const int* __restrict__ tgtp) {
    int t = blockIdx.y;
    int tgt = *tgtp;
    const int* d = e2d + (size_t)t * EE;
    const int* s = e2s + (size_t)t * EE;
    for (int e = blockIdx.x * blockDim.x + threadIdx.x; e < EE; e += gridDim.x * blockDim.x) {
        if (d[e] == tgt) {
            int src = s[e];
            atomicAdd(&g_edge_cnt[t], 1);
            atomicAdd(&g_item_mult[t][src], 1);
            int old = atomicExch(&g_item_flag[t][src], -2);
            if (old == -1) {
                int sl = atomicAdd(&g_num_items[t], 1);
                if (sl < MAXS) g_item_id[t][sl] = src;
            }
            const float* xr = x_item + ((size_t)t * NK + src) * FF;
            #pragma unroll 4
            for (int f = 0; f < FF; f++) atomicAdd(&g_accx[t][f], xr[f]);
        }
    }
}

// ---------------- pass A2: assign slot ids (R1-proven) ----------------
__global__ void k_assign() {
    int t = blockIdx.x;
    if (threadIdx.x == 0 && g_num_items[t] > MAXS) g_num_items[t] = MAXS;
    __syncthreads();
    int n = g_num_items[t];
    for (int k = threadIdx.x; k < n; k += blockDim.x)
        g_item_flag[t][g_item_id[t][k]] = k;
}

// ---------------- pass B: scan e1 (R1-proven scalar strided form) ----------------
__global__ void k_scan_e1(const int* __restrict__ e1s, const int* __restrict__ e1d,
                          const float* __restrict__ x_inf) {
    int t = blockIdx.y;
    const int* d = e1d + (size_t)t * EE;
    const int* s = e1s + (size_t)t * EE;
    for (int e = blockIdx.x * blockDim.x + threadIdx.x; e < EE; e += gridDim.x * blockDim.x) {
        int dst = d[e];
        int sl = g_item_flag[t][dst];
        if (sl >= 0) {
            atomicAdd(&g_item_cnt[t][sl], 1);
            int src = s[e];
            const float* xr = x_inf + ((size_t)t * NI + src) * FF;
            #pragma unroll 4
            for (int f = 0; f < FF; f++) atomicAdd(&g_item_acc[t][sl][f], xr[f]);
        }
    }
}

// ---------------- fused per-t: h_item slots + o_inf[target] + GRU input gates ----------------
__global__ void k_pert(const float* __restrict__ x_item, const float* __restrict__ x_inf,
                       const float* __restrict__ W1a_l, const float* __restrict__ b1a_l,
                       const float* __restrict__ W1a_r,
                       const float* __restrict__ W1b_l, const float* __restrict__ b1b_l,
                       const float* __restrict__ W1b_r,
                       const float* __restrict__ W2b_l, const float* __restrict__ b2b_l,
                       const float* __restrict__ W2b_r,
                       const float* __restrict__ W_ih, const float* __restrict__ b_ih,
                       const int* __restrict__ tgtp) {
    int t = blockIdx.x;
    int tid = threadIdx.x;
    __shared__ float mean[FF], xrow[FF], hinf[HH], meanh[HH], multw[MAXS], xs[OO];
    int n = g_num_items[t];
    if (n > MAXS) n = MAXS;

    // --- h_item for each needed slot ---
    for (int sl = 0; sl < n; sl++) {
        if (tid < FF) {
            float c = fmaxf((float)g_item_cnt[t][sl], 1.0f);
            mean[tid] = g_item_acc[t][sl][tid] / c;
            xrow[tid] = x_item[((size_t)t * NK + g_item_id[t][sl]) * FF + tid];
        }
        __syncthreads();
        int h = tid;
        float a = b1a_l[h];
        const float* wl = W1a_l + (size_t)h * FF;
        const float* wr = W1a_r + (size_t)h * FF;
        #pragma unroll 8
        for (int f = 0; f < FF; f++) a += mean[f] * wl[f] + xrow[f] * wr[f];
        g_hitem[t][sl][h] = fmaxf(a, 0.0f);
        __syncthreads();
    }

    // --- h_inf[target] + weighted mean of h_item over target's e2 edges ---
    int tgt = *tgtp;
    float ec = fmaxf((float)g_edge_cnt[t], 1.0f);
    if (tid < FF) {
        mean[tid] = g_accx[t][tid] / ec;
        xrow[tid] = x_inf[((size_t)t * NI + tgt) * FF + tid];
    }
    for (int k = tid; k < n; k += blockDim.x)
        multw[k] = (float)g_item_mult[t][g_item_id[t][k]];
    __syncthreads();
    {
        int h = tid;
        float v = b1b_l[h];
        const float* wl = W1b_l + (size_t)h * FF;
        const float* wr = W1b_r + (size_t)h * FF;
        #pragma unroll 8
        for (int f = 0; f < FF; f++) v += mean[f] * wl[f] + xrow[f] * wr[f];
        hinf[h] = fmaxf(v, 0.0f);
        float mh = 0.0f;
        for (int k = 0; k < n; k++) mh += multw[k] * g_hitem[t][k][h];
        meanh[h] = mh / ec;
    }
    __syncthreads();

    // --- o_inf[target] -> xs ---
    if (tid < OO) {
        int o = tid;
        float v = b2b_l[o];
        const float* wl = W2b_l + (size_t)o * HH;
        const float* wr = W2b_r + (size_t)o * HH;
        #pragma unroll 8
        for (int h2 = 0; h2 < HH; h2++) v += meanh[h2] * wl[h2] + hinf[h2] * wr[h2];
        xs[o] = v;
    }
    __syncthreads();

    // --- GRU input gates gi = W_ih @ seq[t] + b_ih ---
    for (int row = tid; row < 3 * HH; row += blockDim.x) {
        float v = b_ih[row];
        const float* w = W_ih + (size_t)row * OO;
        #pragma unroll 8
        for (int o = 0; o < OO; o++) v += w[o] * xs[o];
        g_gi[t][row] = v;
    }
}

// ---------------- GRU (8 steps) + head: ONE block, __syncthreads only ----------------
__global__ void __launch_bounds__(256, 1)
k_gru_head(const float* __restrict__ W_hh, const float* __restrict__ b_hh,
           const float* __restrict__ W_att, const float* __restrict__ b_att,
           const float* __restrict__ W_p1, const float* __restrict__ b_p1,
           const float* __restrict__ W_p2, const float* __restrict__ b_p2,
           float* __restrict__ out) {
    int tid = threadIdx.x;
    __shared__ float hs[HH];
    __shared__ float rnn[TT][HH];
    __shared__ float att[TT], ctx[HH], red[HH];

    hs[tid] = 0.0f;
    float bhr = b_hh[tid], bhz = b_hh[HH + tid], bhn = b_hh[2 * HH + tid];
    const float4* wr4 = (const float4*)(W_hh + (size_t)tid * HH);
    const float4* wz4 = (const float4*)(W_hh + (size_t)(HH + tid) * HH);
    const float4* wn4 = (const float4*)(W_hh + (size_t)(2 * HH + tid) * HH);
    __syncthreads();

    for (int t = 0; t < TT; t++) {
        float sr = 0.0f, sz = 0.0f, sn = 0.0f;
        #pragma unroll 8
        for (int k = 0; k < HH / 4; k++) {
            float4 a = wr4[k], b = wz4[k], c = wn4[k];
            float h0 = hs[4 * k + 0], h1 = hs[4 * k + 1];
            float h2 = hs[4 * k + 2], h3 = hs[4 * k + 3];
            sr += a.x * h0 + a.y * h1 + a.z * h2 + a.w * h3;
            sz += b.x * h0 + b.y * h1 + b.z * h2 + b.w * h3;
            sn += c.x * h0 + c.y * h1 + c.z * h2 + c.w * h3;
        }
        float r = 1.0f / (1.0f + expf(-(g_gi[t][tid] + sr + bhr)));
        float z = 1.0f / (1.0f + expf(-(g_gi[t][HH + tid] + sz + bhz)));
        float nn = tanhf(g_gi[t][2 * HH + tid] + r * (sn + bhn));
        float hn = (1.0f - z) * nn + z * hs[tid];
        __syncthreads();
        hs[tid] = hn;
        rnn[t][tid] = hn;
        __syncthreads();
    }

    // --- attention + prediction head ---
    if (tid < TT) {
        float lg = b_att[0];
        for (int h = 0; h < HH; h++) lg += rnn[tid][h] * W_att[h];
        att[tid] = lg;
    }
    __syncthreads();
    if (tid == 0) {
        float m = att[0];
        for (int t = 1; t < TT; t++) m = fmaxf(m, att[t]);
        float s = 0.0f;
        for (int t = 0; t < TT; t++) { att[t] = expf(att[t] - m); s += att[t]; }
        for (int t = 0; t < TT; t++) att[t] /= s;
    }
    __syncthreads();
    {
        float c = 0.0f;
        #pragma unroll
        for (int t = 0; t < TT; t++) c += att[t] * rnn[t][tid];
        ctx[tid] = c;
    }
    __syncthreads();
    if (tid < HH / 2) {
        float v = b_p1[tid];
        const float* wp = W_p1 + (size_t)tid * HH;
        #pragma unroll 8
        for (int h = 0; h < HH; h++) v += wp[h] * ctx[h];
        v = fmaxf(v, 0.0f);
        red[tid] = v * W_p2[tid];
    }
    __syncthreads();
    if (tid == 0) {
        float s = b_p2[0];
        for (int j = 0; j < HH / 2; j++) s += red[j];
        out[0] = s;
    }
}

extern "C" void kernel_launch(void* const* d_in, const int* in_sizes, int n_in,
                              void* d_out, int out_size) {
    const float* x_inf  = (const float*)d_in[0];
    const float* x_item = (const float*)d_in[1];
    const int*   e1s    = (const int*)d_in[2];
    const int*   e1d    = (const int*)d_in[3];
    const int*   e2s    = (const int*)d_in[4];
    const int*   e2d    = (const int*)d_in[5];
    const int*   tgt    = (const int*)d_in[6];
    const float* W1a_l  = (const float*)d_in[7];
    const float* b1a_l  = (const float*)d_in[8];
    const float* W1a_r  = (const float*)d_in[9];
    const float* W1b_l  = (const float*)d_in[10];
    const float* b1b_l  = (const float*)d_in[11];
    const float* W1b_r  = (const float*)d_in[12];
    // d_in[13..15]: W2a_* (dead code — o_item unused by the head)
    const float* W2b_l  = (const float*)d_in[16];
    const float* b2b_l  = (const float*)d_in[17];
    const float* W2b_r  = (const float*)d_in[18];
    const float* W_ih   = (const float*)d_in[19];
    const float* W_hh   = (const float*)d_in[20];
    const float* b_ih   = (const float*)d_in[21];
    const float* b_hh   = (const float*)d_in[22];
    const float* W_att  = (const float*)d_in[23];
    const float* b_att  = (const float*)d_in[24];
    const float* W_p1   = (const float*)d_in[25];
    const float* b_p1   = (const float*)d_in[26];
    const float* W_p2   = (const float*)d_in[27];
    const float* b_p2   = (const float*)d_in[28];
    float* out = (float*)d_out;

    k_init<<<2048, 256>>>();
    dim3 gscan(512, TT);
    k_scan_e2<<<gscan, 256>>>(e2s, e2d, x_item, tgt);
    k_assign<<<TT, 256>>>();
    k_scan_e1<<<gscan, 256>>>(e1s, e1d, x_inf);
    k_pert<<<TT, 256>>>(x_item, x_inf, W1a_l, b1a_l, W1a_r, W1b_l, b1b_l, W1b_r,
                        W2b_l, b2b_l, W2b_r, W_ih, b_ih, tgt);
    k_gru_head<<<1, 256>>>(W_hh, b_hh, W_att, b_att, W_p1, b_p1, W_p2, b_p2, out);
}

// round 6
// speedup vs baseline: 7.6375x; 5.2182x over previous
#include <cuda_runtime.h>
#include <math.h>

#define TT 8
#define NI 20000
#define NK 50000
#define FF 128
#define HH 256
#define OO 128
#define EE 500000
#define MAXS 512

// ---------------- scratch (device globals; no allocation allowed) ----------------
__device__ int   g_item_flag[TT][NK];     // -1 empty, -2 marked, >=0 slot
__device__ int   g_item_mult[TT][NK];     // edge multiplicity (src,target) in e2
__device__ int   g_item_id[TT][MAXS];
__device__ int   g_item_cnt[TT][MAXS];    // e1 in-degree of needed item
__device__ float g_item_acc[TT][MAXS][FF];
__device__ float g_hitem[TT][MAXS][HH];
__device__ int   g_num_items[TT];
__device__ float g_accx[TT][FF];          // sum of x_item over target's e2 edges
__device__ int   g_edge_cnt[TT];
__device__ float g_seq[TT][OO];
__device__ float g_gi[TT][3 * HH];
__device__ float g_hbuf[2][HH];
__device__ float g_rnn[TT][HH];

// ---------------- init / reset ----------------
__global__ void k_init() {
    int idx = blockIdx.x * blockDim.x + threadIdx.x;
    if (idx < TT * NK) {
        ((int*)g_item_flag)[idx] = -1;
        ((int*)g_item_mult)[idx] = 0;
    }
    if (idx < TT * MAXS * FF) ((float*)g_item_acc)[idx] = 0.0f;
    if (idx < TT * MAXS)      ((int*)g_item_cnt)[idx] = 0;
    if (idx < TT * FF)        ((float*)g_accx)[idx] = 0.0f;
    if (idx < TT) { g_edge_cnt[idx] = 0; g_num_items[idx] = 0; }
    if (idx < 2 * HH) ((float*)g_hbuf)[idx] = 0.0f;
}

// ---------------- pass A: scan e2, find target's edges ----------------
__global__ void k_scan_e2(const int* __restrict__ e2s, const int* __restrict__ e2d,
                          const float* __restrict__ x_item, const int* __restrict__ tgtp) {
    int t = blockIdx.y;
    int tgt = *tgtp;
    const int* d = e2d + (size_t)t * EE;
    const int* s = e2s + (size_t)t * EE;
    for (int e = blockIdx.x * blockDim.x + threadIdx.x; e < EE; e += gridDim.x * blockDim.x) {
        if (d[e] == tgt) {
            int src = s[e];
            atomicAdd(&g_edge_cnt[t], 1);
            atomicAdd(&g_item_mult[t][src], 1);
            int old = atomicExch(&g_item_flag[t][src], -2);
            if (old == -1) {
                int sl = atomicAdd(&g_num_items[t], 1);
                if (sl < MAXS) g_item_id[t][sl] = src;
            }
            const float* xr = x_item + ((size_t)t * NK + src) * FF;
            #pragma unroll 4
            for (int f = 0; f < FF; f++) atomicAdd(&g_accx[t][f], xr[f]);
        }
    }
}

// ---------------- pass A2: assign slot ids into flag table ----------------
__global__ void k_assign() {
    int t = blockIdx.x;
    if (threadIdx.x == 0 && g_num_items[t] > MAXS) g_num_items[t] = MAXS;
    __syncthreads();
    int n = g_num_items[t];
    for (int k = threadIdx.x; k < n; k += blockDim.x)
        g_item_flag[t][g_item_id[t][k]] = k;
}

// ---------------- pass B: scan e1, accumulate x_inf into needed items ----------------
__global__ void k_scan_e1(const int* __restrict__ e1s, const int* __restrict__ e1d,
                          const float* __restrict__ x_inf) {
    int t = blockIdx.y;
    const int* d = e1d + (size_t)t * EE;
    const int* s = e1s + (size_t)t * EE;
    for (int e = blockIdx.x * blockDim.x + threadIdx.x; e < EE; e += gridDim.x * blockDim.x) {
        int dst = d[e];
        int sl = g_item_flag[t][dst];
        if (sl >= 0) {
            atomicAdd(&g_item_cnt[t][sl], 1);
            int src = s[e];
            const float* xr = x_inf + ((size_t)t * NI + src) * FF;
            #pragma unroll 4
            for (int f = 0; f < FF; f++) atomicAdd(&g_item_acc[t][sl][f], xr[f]);
        }
    }
}

// ---------------- pass C: h_item for each needed slot ----------------
__global__ void k_hitem(const float* __restrict__ x_item,
                        const float* __restrict__ W1a_l, const float* __restrict__ b1a_l,
                        const float* __restrict__ W1a_r) {
    int t = blockIdx.y;
    __shared__ float mean[FF], xrow[FF];
    for (int sl = blockIdx.x; sl < g_num_items[t]; sl += gridDim.x) {
        int id = g_item_id[t][sl];
        float c = fmaxf((float)g_item_cnt[t][sl], 1.0f);
        if (threadIdx.x < FF) {
            mean[threadIdx.x] = g_item_acc[t][sl][threadIdx.x] / c;
            xrow[threadIdx.x] = x_item[((size_t)t * NK + id) * FF + threadIdx.x];
        }
        __syncthreads();
        int h = threadIdx.x;
        float a = b1a_l[h];
        const float* wl = W1a_l + (size_t)h * FF;
        const float* wr = W1a_r + (size_t)h * FF;
        #pragma unroll 8
        for (int f = 0; f < FF; f++) a += mean[f] * wl[f] + xrow[f] * wr[f];
        g_hitem[t][sl][h] = fmaxf(a, 0.0f);
        __syncthreads();
    }
}

// ---------------- pass D: h_inf[target] + o_inf[target] -> seq[t] ----------------
__global__ void k_oinf(const float* __restrict__ x_inf,
                       const float* __restrict__ W1b_l, const float* __restrict__ b1b_l,
                       const float* __restrict__ W1b_r,
                       const float* __restrict__ W2b_l, const float* __restrict__ b2b_l,
                       const float* __restrict__ W2b_r,
                       const int* __restrict__ tgtp) {
    int t = blockIdx.x;
    int tgt = *tgtp;
    __shared__ float meanx[FF], xt[FF], hinf[HH], meanh[HH], multw[MAXS];
    float ec = fmaxf((float)g_edge_cnt[t], 1.0f);
    int n = g_num_items[t];
    if (threadIdx.x < FF) {
        meanx[threadIdx.x] = g_accx[t][threadIdx.x] / ec;
        xt[threadIdx.x]    = x_inf[((size_t)t * NI + tgt) * FF + threadIdx.x];
    }
    for (int k = threadIdx.x; k < n; k += blockDim.x)
        multw[k] = (float)g_item_mult[t][g_item_id[t][k]];
    __syncthreads();
    int h = threadIdx.x;
    {
        float v = b1b_l[h];
        const float* wl = W1b_l + (size_t)h * FF;
        const float* wr = W1b_r + (size_t)h * FF;
        #pragma unroll 8
        for (int f = 0; f < FF; f++) v += meanx[f] * wl[f] + xt[f] * wr[f];
        hinf[h] = fmaxf(v, 0.0f);
        float mh = 0.0f;
        for (int k = 0; k < n; k++) mh += multw[k] * g_hitem[t][k][h];
        meanh[h] = mh / ec;
    }
    __syncthreads();
    if (threadIdx.x < OO) {
        int o = threadIdx.x;
        float v = b2b_l[o];
        const float* wl = W2b_l + (size_t)o * HH;
        const float* wr = W2b_r + (size_t)o * HH;
        #pragma unroll 8
        for (int h2 = 0; h2 < HH; h2++) v += meanh[h2] * wl[h2] + hinf[h2] * wr[h2];
        g_seq[t][o] = v;
    }
}

// ---------------- GRU input gates (all steps in parallel) ----------------
__global__ void k_gi(const float* __restrict__ W_ih, const float* __restrict__ b_ih) {
    int t = blockIdx.x;
    __shared__ float xs[OO];
    if (threadIdx.x < OO) xs[threadIdx.x] = g_seq[t][threadIdx.x];
    __syncthreads();
    int row = threadIdx.x;  // 0..767
    float v = b_ih[row];
    const float* w = W_ih + (size_t)row * OO;
    #pragma unroll 8
    for (int o = 0; o < OO; o++) v += w[o] * xs[o];
    g_gi[t][row] = v;
}

// ---------------- one GRU step: warp per h-row ----------------
__global__ void k_gru(int t, const float* __restrict__ W_hh, const float* __restrict__ b_hh) {
    const float* hprev = g_hbuf[t & 1];
    float* hnext = g_hbuf[(t + 1) & 1];
    int gwarp = (blockIdx.x * blockDim.x + threadIdx.x) >> 5;
    int lane = threadIdx.x & 31;
    if (gwarp >= HH) return;
    int w = gwarp;
    float sr = 0.0f, sz = 0.0f, sn = 0.0f;
    const float* wr = W_hh + (size_t)w * HH;
    const float* wz = W_hh + (size_t)(HH + w) * HH;
    const float* wn = W_hh + (size_t)(2 * HH + w) * HH;
    #pragma unroll
    for (int j = 0; j < HH / 32; j++) {
        int k = lane + 32 * j;
        float hv = hprev[k];
        sr += wr[k] * hv;
        sz += wz[k] * hv;
        sn += wn[k] * hv;
    }
    #pragma unroll
    for (int off = 16; off > 0; off >>= 1) {
        sr += __shfl_down_sync(0xffffffffu, sr, off);
        sz += __shfl_down_sync(0xffffffffu, sz, off);
        sn += __shfl_down_sync(0xffffffffu, sn, off);
    }
    if (lane == 0) {
        float gh_r = sr + b_hh[w];
        float gh_z = sz + b_hh[HH + w];
        float gh_n = sn + b_hh[2 * HH + w];
        float gi_r = g_gi[t][w];
        float gi_z = g_gi[t][HH + w];
        float gi_n = g_gi[t][2 * HH + w];
        float r = 1.0f / (1.0f + expf(-(gi_r + gh_r)));
        float z = 1.0f / (1.0f + expf(-(gi_z + gh_z)));
        float nn = tanhf(gi_n + r * gh_n);
        float hn = (1.0f - z) * nn + z * hprev[w];
        hnext[w] = hn;
        g_rnn[t][w] = hn;
    }
}

// ---------------- attention + prediction head ----------------
__global__ void k_head(const float* __restrict__ W_att, const float* __restrict__ b_att,
                       const float* __restrict__ W_p1, const float* __restrict__ b_p1,
                       const float* __restrict__ W_p2, const float* __restrict__ b_p2,
                       float* __restrict__ out) {
    __shared__ float att[TT], ctx[HH], red[HH];
    int tid = threadIdx.x;
    if (tid < TT) {
        float lg = b_att[0];
        for (int h = 0; h < HH; h++) lg += g_rnn[tid][h] * W_att[h];
        att[tid] = lg;
    }
    __syncthreads();
    if (tid == 0) {
        float m = att[0];
        for (int t = 1; t < TT; t++) m = fmaxf(m, att[t]);
        float s = 0.0f;
        for (int t = 0; t < TT; t++) { att[t] = expf(att[t] - m); s += att[t]; }
        for (int t = 0; t < TT; t++) att[t] /= s;
    }
    __syncthreads();
    {
        float c = 0.0f;
        #pragma unroll
        for (int t = 0; t < TT; t++) c += att[t] * g_rnn[t][tid];
        ctx[tid] = c;
    }
    __syncthreads();
    if (tid < HH / 2) {
        float v = b_p1[tid];
        const float* w = W_p1 + (size_t)tid * HH;
        #pragma unroll 8
        for (int h = 0; h < HH; h++) v += w[h] * ctx[h];
        v = fmaxf(v, 0.0f);
        red[tid] = v * W_p2[tid];
    }
    __syncthreads();
    if (tid == 0) {
        float s = b_p2[0];
        for (int j = 0; j < HH / 2; j++) s += red[j];
        out[0] = s;
    }
}

extern "C" void kernel_launch(void* const* d_in, const int* in_sizes, int n_in,
                              void* d_out, int out_size) {
    const float* x_inf  = (const float*)d_in[0];
    const float* x_item = (const float*)d_in[1];
    const int*   e1s    = (const int*)d_in[2];
    const int*   e1d    = (const int*)d_in[3];
    const int*   e2s    = (const int*)d_in[4];
    const int*   e2d    = (const int*)d_in[5];
    const int*   tgt    = (const int*)d_in[6];
    const float* W1a_l  = (const float*)d_in[7];
    const float* b1a_l  = (const float*)d_in[8];
    const float* W1a_r  = (const float*)d_in[9];
    const float* W1b_l  = (const float*)d_in[10];
    const float* b1b_l  = (const float*)d_in[11];
    const float* W1b_r  = (const float*)d_in[12];
    // d_in[13..15]: W2a_* (dead code in reference — o_item unused)
    const float* W2b_l  = (const float*)d_in[16];
    const float* b2b_l  = (const float*)d_in[17];
    const float* W2b_r  = (const float*)d_in[18];
    const float* W_ih   = (const float*)d_in[19];
    const float* W_hh   = (const float*)d_in[20];
    const float* b_ih   = (const float*)d_in[21];
    const float* b_hh   = (const float*)d_in[22];
    const float* W_att  = (const float*)d_in[23];
    const float* b_att  = (const float*)d_in[24];
    const float* W_p1   = (const float*)d_in[25];
    const float* b_p1   = (const float*)d_in[26];
    const float* W_p2   = (const float*)d_in[27];
    const float* b_p2   = (const float*)d_in[28];
    float* out = (float*)d_out;

    k_init<<<2048, 256>>>();
    dim3 gscan(512, TT);
    k_scan_e2<<<gscan, 256>>>(e2s, e2d, x_item, tgt);
    k_assign<<<TT, 256>>>();
    k_scan_e1<<<gscan, 256>>>(e1s, e1d, x_inf);
    k_hitem<<<dim3(64, TT), 256>>>(x_item, W1a_l, b1a_l, W1a_r);
    k_oinf<<<TT, 256>>>(x_inf, W1b_l, b1b_l, W1b_r, W2b_l, b2b_l, W2b_r, tgt);
    k_gi<<<TT, 3 * HH>>>(W_ih, b_ih);
    for (int t = 0; t < TT; t++)
        k_gru<<<32, 256>>>(t, W_hh, b_hh);
    k_head<<<1, 256>>>(W_att, b_att, W_p1, b_p1, W_p2, b_p2, out);
}